// round 9
// baseline (speedup 1.0000x reference)
#include <cuda_runtime.h>
#include <cuda_fp16.h>
#include <cstdint>
#include <math.h>

#define B_    64
#define T_    1024
#define D_    512
#define KTAP  5
#define U_    256
#define G4_   1024
#define TP_   (T_ + 4)
#define XPD_  (TP_ * D_)
#define RNN_CTAS 64

#define BM    128
#define BN    128
#define KC    32                 // fp16 k per chunk
#define ROWB  80                 // smem row stride (bytes) -> conflict-free ldmatrix
#define TILEB (128 * ROWB)       // 10240 B per tile
#define STAGEB (3 * TILEB)       // A, BH, BL
#define NSTG  3
#define GSMEM (NSTG * STAGEB)    // 90 KB -> 2 CTAs/SM

// ---------------- scratch ----------------
__device__ uint16_t g_x0[(size_t)B_ * XPD_];        // fp16 activation planes
__device__ uint16_t g_x1[(size_t)B_ * XPD_];
__device__ uint16_t g_wch[(size_t)3 * 512 * 2560];  // conv weights hi [i][n][kk]
__device__ uint16_t g_wcl[(size_t)3 * 512 * 2560];  // conv weights lo
__device__ uint16_t g_wlh[(size_t)2 * 1024 * 512];  // lstm kernels hi [dir][n][d]
__device__ uint16_t g_wll[(size_t)2 * 1024 * 512];  // lstm kernels lo
__device__ float    g_pre_f[(size_t)T_ * B_ * G4_];
__device__ float    g_pre_b[(size_t)T_ * B_ * G4_];
__device__ float    g_h[2][2][B_ * U_];
__device__ unsigned g_bar[2];

// ---------------- helpers ----------------
__device__ __forceinline__ uint32_t smem_u32(const void* p) {
    uint32_t a;
    asm("{ .reg .u64 t; cvta.to.shared.u64 t, %1; cvt.u32.u64 %0, t; }" : "=r"(a) : "l"(p));
    return a;
}
__device__ __forceinline__ uint16_t f2h(float v) {
    return __half_as_ushort(__float2half(v));
}
__device__ __forceinline__ void split_h16(float v, uint16_t& h, uint16_t& l) {
    __half hh = __float2half(v);
    float hf = __half2float(hh);
    h = __half_as_ushort(hh);
    l = __half_as_ushort(__float2half(v - hf));
}
#define CP16(dst, src) \
    asm volatile("cp.async.cg.shared.global [%0], [%1], 16;" :: "r"(dst), "l"(src))
#define CP_COMMIT() asm volatile("cp.async.commit_group;" ::: "memory")
#define CP_WAIT(N)  asm volatile("cp.async.wait_group %0;" :: "n"(N) : "memory")
#define LDM_X4(R0, R1, R2, R3, ADDR)                                            \
    asm volatile("ldmatrix.sync.aligned.m8n8.x4.shared.b16 {%0,%1,%2,%3}, [%4];"\
        : "=r"(R0), "=r"(R1), "=r"(R2), "=r"(R3) : "r"(ADDR))
__device__ __forceinline__ void mma_f16(float* c, const uint32_t* a, const uint32_t* b) {
    asm volatile(
        "mma.sync.aligned.m16n8k16.row.col.f32.f16.f16.f32 "
        "{%0,%1,%2,%3}, {%4,%5,%6,%7}, {%8,%9}, {%0,%1,%2,%3};"
        : "+f"(c[0]), "+f"(c[1]), "+f"(c[2]), "+f"(c[3])
        : "r"(a[0]), "r"(a[1]), "r"(a[2]), "r"(a[3]), "r"(b[0]), "r"(b[1]));
}
// packed fp32x2 (Blackwell)
#define PACK2(d, lo, hi) asm("mov.b64 %0, {%1, %2};" : "=l"(d) : "f"(lo), "f"(hi))
#define UNPACK2(lo, hi, s) asm("mov.b64 {%0, %1}, %2;" : "=f"(lo), "=f"(hi) : "l"(s))
#define FMA2(d, a, b) asm("fma.rn.f32x2 %0, %1, %2, %0;" : "+l"(d) : "l"(a), "l"(b))

// ---------------- init ----------------
__global__ void init_kernel() {
    int idx = blockIdx.x * blockDim.x + threadIdx.x;
    int nh = B_ * 4 * D_;
    if (idx < nh) {
        int b = idx / (4 * D_);
        int r = (idx / D_) & 3;
        int d = idx % D_;
        int row = (r < 2) ? r : (TP_ - 4 + r);
        size_t o = (size_t)b * XPD_ + (size_t)row * D_ + d;
        g_x0[o] = 0; g_x1[o] = 0;
    }
    if (idx < 2 * 2 * B_ * U_) ((float*)g_h)[idx] = 0.f;
    if (idx < 2) g_bar[idx] = 0u;
}

// ---------------- pack input (single fp16) ----------------
__global__ void pad_pack(const float* __restrict__ in) {
    size_t total = (size_t)B_ * T_ * D_;
    for (size_t idx = (size_t)blockIdx.x * blockDim.x + threadIdx.x;
         idx < total; idx += (size_t)gridDim.x * blockDim.x) {
        size_t b = idx / ((size_t)T_ * D_);
        size_t r = idx % ((size_t)T_ * D_);
        size_t t = r / D_, d = r % D_;
        g_x0[b * XPD_ + (t + 2) * D_ + d] = f2h(in[idx]);
    }
}

// ---------------- transpose + split weights (fp16 hi/lo) ----------------
__global__ void wprep(const float* __restrict__ convk,
                      const float* __restrict__ wkf, const float* __restrict__ wkb) {
    const size_t CONVN = (size_t)3 * 512 * 2560;
    const size_t LSTMN = (size_t)1024 * 512;
    size_t total = CONVN + 2 * LSTMN;
    for (size_t idx = (size_t)blockIdx.x * blockDim.x + threadIdx.x;
         idx < total; idx += (size_t)gridDim.x * blockDim.x) {
        uint16_t h, l;
        if (idx < CONVN) {
            size_t i = idx / ((size_t)512 * 2560);
            size_t r = idx % ((size_t)512 * 2560);
            size_t n = r / 2560, kk = r % 2560;
            size_t tap = kk >> 9, din = kk & 511;
            split_h16(convk[(((i * KTAP + tap) * D_) + din) * D_ + n], h, l);
            g_wch[idx] = h; g_wcl[idx] = l;
        } else if (idx < CONVN + LSTMN) {
            size_t j = idx - CONVN;
            size_t n = j >> 9, d = j & 511;
            split_h16(wkf[d * G4_ + n], h, l);
            g_wlh[j] = h; g_wll[j] = l;
        } else {
            size_t j = idx - CONVN - LSTMN;
            size_t n = j >> 9, d = j & 511;
            split_h16(wkb[d * G4_ + n], h, l);
            g_wlh[LSTMN + j] = h; g_wll[LSTMN + j] = l;
        }
    }
}

// ---------------- fp16 2-term warp-MMA GEMM (A single, B split hi/lo) ----------------
template <int MODE>
__global__ __launch_bounds__(256, 2) void mma_gemm(
    const uint16_t* __restrict__ Ap,
    const uint16_t* __restrict__ Bh, const uint16_t* __restrict__ Bl,
    int KKtot,
    const float* __restrict__ bias,
    const float* __restrict__ bng, const float* __restrict__ bnb,
    const float* __restrict__ bnm, const float* __restrict__ bnv,
    uint16_t* __restrict__ Cp, float* __restrict__ Cf)
{
    extern __shared__ char smraw[];
    const uint32_t sbase = smem_u32(smraw);

    const int tid = threadIdx.x;
    const int wid = tid >> 5, lane = tid & 31;
    const int bz = blockIdx.z;
    const int t0 = blockIdx.y * BM;
    const int n0 = blockIdx.x * BN;
    const int wm = wid & 1;
    const int wn = wid >> 1;

    const uint32_t a_off = (uint32_t)((wm * 64 + (lane & 15)) * ROWB + (lane >> 4) * 16);
    const uint32_t b_off = (uint32_t)((wn * 32 + (lane & 7) + ((lane >> 4) << 3)) * ROWB
                                      + ((lane >> 3) & 1) * 16);

    const uint16_t* Ab = Ap + (size_t)bz * XPD_;
    const int NCH = KKtot / KC;

    float cacc[4][4][4];
#pragma unroll
    for (int i = 0; i < 4; i++)
#pragma unroll
        for (int j = 0; j < 4; j++)
#pragma unroll
            for (int q = 0; q < 4; q++) cacc[i][j][q] = 0.f;

    auto issue = [&](int cc) {
        const int st = cc % NSTG;
        const int kk0 = cc * KC;
        const int tap = kk0 >> 9;
        const int d0 = kk0 & 511;
        const uint32_t sb = sbase + st * STAGEB;
#pragma unroll
        for (int half = 0; half < 2; half++) {
            const int s = tid + half * 256;
            const int row = s >> 2, seg = s & 3;
            const uint32_t doff = (uint32_t)(row * ROWB + seg * 16);
            const size_t aoff = (size_t)(t0 + row + tap) * D_ + d0 + seg * 8;
            const size_t boff = (size_t)(n0 + row) * KKtot + kk0 + seg * 8;
            CP16(sb + doff,             Ab + aoff);
            CP16(sb + TILEB + doff,     Bh + boff);
            CP16(sb + 2 * TILEB + doff, Bl + boff);
        }
        CP_COMMIT();
    };

    auto compute = [&](int st) {
        const uint32_t SB = sbase + st * STAGEB;
#pragma unroll
        for (int k16 = 0; k16 < 2; k16++) {
            const uint32_t kof = k16 * 32;
            uint32_t bh[4][2], bl[4][2];
#pragma unroll
            for (int nfp = 0; nfp < 2; nfp++) {
                uint32_t bd = SB + TILEB + b_off + nfp * (16 * ROWB) + kof;
                LDM_X4(bh[2 * nfp][0], bh[2 * nfp][1], bh[2 * nfp + 1][0], bh[2 * nfp + 1][1], bd);
                LDM_X4(bl[2 * nfp][0], bl[2 * nfp][1], bl[2 * nfp + 1][0], bl[2 * nfp + 1][1], bd + TILEB);
            }
#pragma unroll
            for (int mf = 0; mf < 4; mf++) {
                uint32_t af[4];
                uint32_t ad = SB + a_off + mf * (16 * ROWB) + kof;
                LDM_X4(af[0], af[1], af[2], af[3], ad);
#pragma unroll
                for (int nf = 0; nf < 4; nf++) {
                    mma_f16(cacc[mf][nf], af, bh[nf]);
                    mma_f16(cacc[mf][nf], af, bl[nf]);
                }
            }
        }
    };

    issue(0);
    issue(1);

    for (int cc = 0; cc < NCH; cc++) {
        CP_WAIT(1);
        __syncthreads();
        if (cc + 2 < NCH) issue(cc + 2);
        else CP_COMMIT();
        compute(cc % NSTG);
    }

    // ---------------- epilogue ----------------
    const int r0 = lane >> 2;
    const int cq = (lane & 3) * 2;
    float mul0[4], mul1[4], add0[4], add1[4];
#pragma unroll
    for (int nf = 0; nf < 4; nf++) {
        int n = n0 + wn * 32 + nf * 8 + cq;
        float b0 = __ldg(&bias[n]), b1 = __ldg(&bias[n + 1]);
        if (MODE == 0) {
            float s0 = __ldg(&bng[n]) * rsqrtf(__ldg(&bnv[n]) + 1e-3f);
            float s1 = __ldg(&bng[n + 1]) * rsqrtf(__ldg(&bnv[n + 1]) + 1e-3f);
            mul0[nf] = s0; mul1[nf] = s1;
            add0[nf] = s0 * (b0 - __ldg(&bnm[n])) + __ldg(&bnb[n]);
            add1[nf] = s1 * (b1 - __ldg(&bnm[n + 1])) + __ldg(&bnb[n + 1]);
        } else {
            mul0[nf] = 1.f; mul1[nf] = 1.f;
            add0[nf] = b0;  add1[nf] = b1;
        }
    }

#pragma unroll
    for (int mf = 0; mf < 4; mf++) {
#pragma unroll
        for (int half = 0; half < 2; half++) {
            int m = wm * 64 + mf * 16 + r0 + half * 8;
#pragma unroll
            for (int nf = 0; nf < 4; nf++) {
                float v0 = fmaf(cacc[mf][nf][2 * half + 0], mul0[nf], add0[nf]);
                float v1 = fmaf(cacc[mf][nf][2 * half + 1], mul1[nf], add1[nf]);
                int nc = n0 + wn * 32 + nf * 8 + cq;
                if (MODE == 0) {
                    v0 = fmaxf(v0, 0.f);
                    v1 = fmaxf(v1, 0.f);
                    size_t off = (size_t)bz * XPD_ + (size_t)(t0 + m + 2) * D_ + nc;
                    *(uint32_t*)(Cp + off) = (uint32_t)f2h(v0) | ((uint32_t)f2h(v1) << 16);
                } else {
                    int t = t0 + m;
                    size_t off = (MODE == 1)
                        ? ((size_t)t * B_ + bz) * G4_ + nc
                        : ((size_t)(T_ - 1 - t) * B_ + bz) * G4_ + nc;
                    *(float2*)(Cf + off) = make_float2(v0, v1);
                }
            }
        }
    }
}

// ---------------- persistent bi-LSTM recurrence ----------------
// Warp-private chunked h staging overlapped with f32x2 gate GEMV.
// Warp w stages + consumes h rows [8w, 8w+8); 4 chunks of 64 units each.
__global__ __launch_bounds__(256) void lstm_kernel(
    const float* __restrict__ pre_f, const float* __restrict__ pre_b,
    const float* __restrict__ wr_f,  const float* __restrict__ wr_b,
    float* __restrict__ out)
{
    extern __shared__ float sm[];
    float* sW = sm;            // [128][4][4][2] = 4096 floats
    float* sH = sm + 4096;     // [64][260]

    const int bx  = blockIdx.x;
    const int dir = bx >> 6;
    const int u0  = (bx & 63) << 2;
    const float* pre = dir ? pre_b : pre_f;
    const float* Wr  = dir ? wr_b  : wr_f;
    unsigned* bar = &g_bar[dir];

    const int tid = threadIdx.x;
    const int lane = tid & 31;
    const int b = tid >> 2, q = tid & 3, u = u0 + q;

    // paired weight layout: idx = k2*32 + qq*8 + g*2 + par, k = 2*k2 + par
    for (int idx = tid; idx < 4096; idx += 256) {
        int par = idx & 1;
        int rest = idx >> 1;
        int g = rest & 3, qq = (rest >> 2) & 3, k2 = rest >> 4;
        int k = 2 * k2 + par;
        sW[idx] = Wr[(size_t)k * G4_ + g * U_ + u0 + qq];
    }

    float c = 0.f;
    float* h0 = &g_h[dir][0][0];
    float* h1 = &g_h[dir][1][0];
    __syncthreads();

    const uint64_t* wbase = (const uint64_t*)(sW) + q * 4;

    // staging addresses: lane covers (row = b, 4 float4 segments per chunk)
    const int segb = (lane & 3) * 4;          // float offset of segment within chunk
    const float* hrow_g;                      // set per step
    float* srow = &sH[b * 260];               // this thread's row (warp-private block)

    for (int t = 0; t < T_; t++) {
        // prefetch pre-activations (DRAM; consumed ~2500 cyc later)
        const float* p = pre + ((size_t)t * B_ + b) * G4_ + u;
        float z0 = __ldg(&p[0]);
        float z1 = __ldg(&p[U_]);
        float z2 = __ldg(&p[2 * U_]);
        float z3 = __ldg(&p[3 * U_]);

        const float* hr = ((t + 1) & 1) ? h1 : h0;
        hrow_g = hr + b * U_;

        uint64_t ai, af, ag, ao;
        PACK2(ai, z0, 0.f);
        PACK2(af, z1, 0.f);
        PACK2(ag, z2, 0.f);
        PACK2(ao, z3, 0.f);

        // chunk 0: load + store + syncwarp
        float4 rg[4];
#pragma unroll
        for (int i = 0; i < 4; i++)
            rg[i] = __ldcg((const float4*)(hrow_g + 0 * 64 + segb + i * 16));
#pragma unroll
        for (int i = 0; i < 4; i++)
            *(float4*)(srow + 0 * 64 + segb + i * 16) = rg[i];
        __syncwarp();

#pragma unroll
        for (int ch = 0; ch < 4; ch++) {
            if (ch < 3) {
#pragma unroll
                for (int i = 0; i < 4; i++)
                    rg[i] = __ldcg((const float4*)(hrow_g + (ch + 1) * 64 + segb + i * 16));
            }
            // compute k2 in [ch*32, ch*32+32)
#pragma unroll
            for (int kk = 0; kk < 32; kk++) {
                const int k2 = ch * 32 + kk;
                uint64_t h2 = *(const uint64_t*)(srow + k2 * 2);
                const uint64_t* wp = wbase + k2 * 16;
                FMA2(ai, h2, wp[0]);
                FMA2(af, h2, wp[1]);
                FMA2(ag, h2, wp[2]);
                FMA2(ao, h2, wp[3]);
            }
            if (ch < 3) {
#pragma unroll
                for (int i = 0; i < 4; i++)
                    *(float4*)(srow + (ch + 1) * 64 + segb + i * 16) = rg[i];
                __syncwarp();
            }
        }

        float e0, e1;
        UNPACK2(e0, e1, ai); z0 = e0 + e1;
        UNPACK2(e0, e1, af); z1 = e0 + e1;
        UNPACK2(e0, e1, ag); z2 = e0 + e1;
        UNPACK2(e0, e1, ao); z3 = e0 + e1;

        float ig = 1.f / (1.f + __expf(-z0));
        float fg = 1.f / (1.f + __expf(-z1));
        float gg = tanhf(z2);
        float og = 1.f / (1.f + __expf(-z3));
        c = fg * c + ig * gg;
        float h = og * tanhf(c);

        float* hw = (t & 1) ? h1 : h0;
        hw[b * U_ + u] = h;
        int tout = dir ? (T_ - 1 - t) : t;
        out[((size_t)b * T_ + tout) * (2 * U_) + dir * U_ + u] = h;

        __syncthreads();
        if (tid == 0) {
            __threadfence();
            atomicAdd(bar, 1u);
            unsigned target = (unsigned)(t + 1) * RNN_CTAS;
            unsigned v;
            do {
                asm volatile("ld.global.acquire.gpu.u32 %0, [%1];" : "=r"(v) : "l"(bar));
            } while (v < target);
        }
        __syncthreads();
    }
}

// ---------------- launcher ----------------
extern "C" void kernel_launch(void* const* d_in, const int* in_sizes, int n_in,
                              void* d_out, int out_size)
{
    const float* inputs = (const float*)d_in[0];
    const float* convk  = (const float*)d_in[1];
    const float* convb  = (const float*)d_in[2];
    const float* bng    = (const float*)d_in[3];
    const float* bnb    = (const float*)d_in[4];
    const float* bnm    = (const float*)d_in[5];
    const float* bnv    = (const float*)d_in[6];
    const float* wk_f   = (const float*)d_in[7];
    const float* wr_f   = (const float*)d_in[8];
    const float* bi_f   = (const float*)d_in[9];
    const float* wk_b   = (const float*)d_in[10];
    const float* wr_b   = (const float*)d_in[11];
    const float* bi_b   = (const float*)d_in[12];
    float* out = (float*)d_out;

    uint16_t *x0, *x1, *wch, *wcl, *wlh, *wll;
    float *pre_f, *pre_b;
    cudaGetSymbolAddress((void**)&x0, g_x0);
    cudaGetSymbolAddress((void**)&x1, g_x1);
    cudaGetSymbolAddress((void**)&wch, g_wch);
    cudaGetSymbolAddress((void**)&wcl, g_wcl);
    cudaGetSymbolAddress((void**)&wlh, g_wlh);
    cudaGetSymbolAddress((void**)&wll, g_wll);
    cudaGetSymbolAddress((void**)&pre_f, g_pre_f);
    cudaGetSymbolAddress((void**)&pre_b, g_pre_b);

    cudaFuncSetAttribute(mma_gemm<0>, cudaFuncAttributeMaxDynamicSharedMemorySize, GSMEM);
    cudaFuncSetAttribute(mma_gemm<1>, cudaFuncAttributeMaxDynamicSharedMemorySize, GSMEM);
    cudaFuncSetAttribute(mma_gemm<2>, cudaFuncAttributeMaxDynamicSharedMemorySize, GSMEM);

    init_kernel<<<512, 256>>>();
    pad_pack<<<8192, 256>>>(inputs);
    wprep<<<8192, 256>>>(convk, wk_f, wk_b);

    const size_t wcs = (size_t)512 * 2560;
    dim3 gc(D_ / BN, T_ / BM, B_);           // (4, 8, 64)
    mma_gemm<0><<<gc, 256, GSMEM>>>(x0, wch + 0 * wcs, wcl + 0 * wcs, KTAP * D_,
                                    convb + 0 * D_, bng + 0 * D_, bnb + 0 * D_,
                                    bnm + 0 * D_, bnv + 0 * D_, x1, nullptr);
    mma_gemm<0><<<gc, 256, GSMEM>>>(x1, wch + 1 * wcs, wcl + 1 * wcs, KTAP * D_,
                                    convb + 1 * D_, bng + 1 * D_, bnb + 1 * D_,
                                    bnm + 1 * D_, bnv + 1 * D_, x0, nullptr);
    mma_gemm<0><<<gc, 256, GSMEM>>>(x0, wch + 2 * wcs, wcl + 2 * wcs, KTAP * D_,
                                    convb + 2 * D_, bng + 2 * D_, bnb + 2 * D_,
                                    bnm + 2 * D_, bnv + 2 * D_, x1, nullptr);

    const size_t wls = (size_t)1024 * 512;
    dim3 gl(G4_ / BN, T_ / BM, B_);          // (8, 8, 64)
    mma_gemm<1><<<gl, 256, GSMEM>>>(x1 + 2 * D_, wlh + 0 * wls, wll + 0 * wls, D_,
                                    bi_f, bng, bnb, bnm, bnv, nullptr, pre_f);
    mma_gemm<2><<<gl, 256, GSMEM>>>(x1 + 2 * D_, wlh + 1 * wls, wll + 1 * wls, D_,
                                    bi_b, bng, bnb, bnm, bnv, nullptr, pre_b);

    const int lstm_smem = (4096 + 64 * 260) * (int)sizeof(float);
    cudaFuncSetAttribute(lstm_kernel, cudaFuncAttributeMaxDynamicSharedMemorySize, lstm_smem);
    lstm_kernel<<<2 * RNN_CTAS, 256, lstm_smem>>>(pre_f, pre_b, wr_f, wr_b, out);
}